// round 11
// baseline (speedup 1.0000x reference)
#include <cuda_runtime.h>
#include <math.h>

#define NN   50000
#define FIN  256
#define H1N  8
#define F1   256
#define NEG  0.2f
#define EMAX 900000
#define FULL 0xffffffffu

// ---------------- scratch ----------------
__device__ __align__(256) float g_h1[NN * F1];
__device__ __align__(256) float g_el1[NN * H1N];
__device__ __align__(256) float g_er1[NN * H1N];
__device__ __align__(256) float g_x1[NN * F1];
__device__ __align__(256) float g_h2res[NN * 128];   // [h2 (64) | residual (64)]
__device__ __align__(256) float g_el2[NN];
__device__ __align__(256) float g_er2[NN];
__device__ __align__(256) float g_Bcat[FIN * 128];
__device__ int g_deg[NN];
__device__ int g_off[NN + 1];
__device__ int g_us[EMAX];

// ---------------- CSR build ----------------
__global__ void k_hist(const int* __restrict__ dst, int E, int* __restrict__ deg) {
    int i = blockIdx.x * blockDim.x + threadIdx.x;
    if (i < E) atomicAdd(&deg[dst[i]], 1);
}

__global__ void k_scan(const int* __restrict__ deg, int* __restrict__ off, int n) {
    __shared__ int wsum[32];
    __shared__ int carry;
    int tid = threadIdx.x, lane = tid & 31, wid = tid >> 5;
    if (tid == 0) carry = 0;
    __syncthreads();
    for (int base = 0; base < n; base += 1024) {
        int i = base + tid;
        int v = (i < n) ? deg[i] : 0;
        int x = v;
        #pragma unroll
        for (int o = 1; o < 32; o <<= 1) {
            int y = __shfl_up_sync(FULL, x, o);
            if (lane >= o) x += y;
        }
        if (lane == 31) wsum[wid] = x;
        __syncthreads();
        if (wid == 0) {
            int w = wsum[lane];
            #pragma unroll
            for (int o = 1; o < 32; o <<= 1) {
                int y = __shfl_up_sync(FULL, w, o);
                if (lane >= o) w += y;
            }
            wsum[lane] = w;
        }
        __syncthreads();
        int incl = x + (wid ? wsum[wid - 1] : 0) + carry;
        if (i < n) off[i] = incl - v;
        __syncthreads();
        if (tid == 1023) carry = incl;
        __syncthreads();
    }
    if (tid == 0) off[n] = carry;
}

__global__ void k_scatter(const int* __restrict__ src, const int* __restrict__ dst,
                          int E, const int* __restrict__ off, int* __restrict__ cur,
                          int* __restrict__ us) {
    int i = blockIdx.x * blockDim.x + threadIdx.x;
    if (i < E) {
        int d = dst[i];
        int p = off[d] + atomicAdd(&cur[d], 1);
        us[p] = src[i];
    }
}

// ---------------- TF32 GEMM: smem tiles stored in MMA-fragment order ------------
// A-frag: AsF[mrow16][ks][lane] = uint4 {(g,q),(g+8,q),(g,q+4),(g+8,q+4)} -> 1 LDS.128
// B-frag: BsF[nb8][ks][lane]    = uint2 {(cb+g,q),(cb+g,q+4)}             -> 1 LDS.64
__device__ __forceinline__ unsigned f2tf(float x) {
    unsigned u;
    asm("cvt.rna.tf32.f32 %0, %1;" : "=r"(u) : "f"(x));
    return u;
}

__device__ __forceinline__ void mma_tf32(float* d, const unsigned* a, const unsigned* b) {
    asm volatile(
        "mma.sync.aligned.m16n8k8.row.col.f32.tf32.tf32.f32 "
        "{%0,%1,%2,%3}, {%4,%5,%6,%7}, {%8,%9}, {%0,%1,%2,%3};\n"
        : "+f"(d[0]), "+f"(d[1]), "+f"(d[2]), "+f"(d[3])
        : "r"(a[0]), "r"(a[1]), "r"(a[2]), "r"(a[3]), "r"(b[0]), "r"(b[1]));
}

__global__ __launch_bounds__(256)
void k_mma_gemm(const float* __restrict__ A, const float* __restrict__ B,
                float* __restrict__ C, int M, int N, int K) {
    __shared__ uint4 AsF[8 * 4 * 32];   // 16 KB: [mrow16][ks][lane]
    __shared__ uint2 BsF[8 * 4 * 32];   //  8 KB: [nb8][ks][lane]
    unsigned* AsW = (unsigned*)AsF;
    unsigned* BsW = (unsigned*)BsF;

    int t = threadIdx.x;
    int lane = t & 31;
    int warp = t >> 5;
    int g = lane >> 2, q = lane & 3;
    int warpM = warp & 3, warpN = warp >> 2;   // 4x2 warps, warp tile 32x32
    int bm = blockIdx.x * 128, bn = blockIdx.y * 64;

    float4 avs[4], bvs[2];
    float acc[2][4][4] = {};

    auto loadA = [&](int kt) {
        #pragma unroll
        for (int i = 0; i < 4; i++) {
            int idx = t + i * 256;
            int r = idx >> 3, c4 = (idx & 7) * 4;
            float4 v = make_float4(0.f, 0.f, 0.f, 0.f);
            if (bm + r < M)
                v = *(const float4*)&A[(size_t)(bm + r) * K + kt + c4];
            avs[i] = v;
        }
    };
    auto loadB = [&](int kt) {
        #pragma unroll
        for (int i = 0; i < 2; i++) {
            int idx = t + i * 256;
            int r = idx >> 4, c4 = (idx & 15) * 4;
            bvs[i] = *(const float4*)&B[(size_t)(kt + r) * N + bn + c4];
        }
    };
    auto stage = [&]() {
        // A: value A[r][k] -> frag (r>>4, k>>3), lane (r&7)*4 + (k&3),
        //    j = ((r>>3)&1) | (((k>>2)&1)<<1).   Thread holds k = c4..c4+3 (same ks/hi).
        #pragma unroll
        for (int i = 0; i < 4; i++) {
            int idx = t + i * 256;
            int r = idx >> 3, c4 = (idx & 7) * 4;
            int mrow16 = r >> 4;
            int ga = r & 7;
            int j = ((r >> 3) & 1) | (((c4 >> 2) & 1) << 1);
            int ks = c4 >> 3;
            unsigned base = (unsigned)(((mrow16 * 4 + ks) * 32 + ga * 4) * 4 + j);
            AsW[base + 0 * 4] = f2tf(avs[i].x);
            AsW[base + 1 * 4] = f2tf(avs[i].y);
            AsW[base + 2 * 4] = f2tf(avs[i].z);
            AsW[base + 3 * 4] = f2tf(avs[i].w);
        }
        // B: value B[k][n] -> frag (n>>3, k>>3), lane (n&7)*4 + (k&3), j = (k>>2)&1.
        //    Thread holds n = c4..c4+3 (same nb8).
        #pragma unroll
        for (int i = 0; i < 2; i++) {
            int idx = t + i * 256;
            int r = idx >> 4, c4 = (idx & 15) * 4;
            int ks = r >> 3;
            int qb = r & 3;
            int j = (r >> 2) & 1;
            int nb8 = c4 >> 3;
            int gb0 = c4 & 7;
            unsigned base = (unsigned)(((nb8 * 4 + ks) * 32 + gb0 * 4 + qb) * 2 + j);
            BsW[base + 0 * 8] = f2tf(bvs[i].x);
            BsW[base + 1 * 8] = f2tf(bvs[i].y);
            BsW[base + 2 * 8] = f2tf(bvs[i].z);
            BsW[base + 3 * 8] = f2tf(bvs[i].w);
        }
    };

    loadA(0); loadB(0);
    stage();
    __syncthreads();

    for (int kt = 0; kt < K; kt += 32) {
        bool nxt = (kt + 32) < K;
        if (nxt) { loadA(kt + 32); loadB(kt + 32); }

        #pragma unroll
        for (int ks = 0; ks < 4; ks++) {
            uint4 afv[2];
            uint2 bfv[4];
            #pragma unroll
            for (int mt = 0; mt < 2; mt++)
                afv[mt] = AsF[((warpM * 2 + mt) * 4 + ks) * 32 + lane];
            #pragma unroll
            for (int nt = 0; nt < 4; nt++)
                bfv[nt] = BsF[((warpN * 4 + nt) * 4 + ks) * 32 + lane];
            #pragma unroll
            for (int mt = 0; mt < 2; mt++)
                #pragma unroll
                for (int nt = 0; nt < 4; nt++)
                    mma_tf32(acc[mt][nt], (const unsigned*)&afv[mt], (const unsigned*)&bfv[nt]);
        }
        if (nxt) {
            __syncthreads();
            stage();
            __syncthreads();
        }
    }

    #pragma unroll
    for (int mt = 0; mt < 2; mt++) {
        int r0 = bm + warpM * 32 + mt * 16 + g;
        #pragma unroll
        for (int nt = 0; nt < 4; nt++) {
            int c = bn + warpN * 32 + nt * 8 + q * 2;
            if (r0 < M)
                *(float2*)&C[(size_t)r0 * N + c] = make_float2(acc[mt][nt][0], acc[mt][nt][1]);
            if (r0 + 8 < M)
                *(float2*)&C[(size_t)(r0 + 8) * N + c] = make_float2(acc[mt][nt][2], acc[mt][nt][3]);
        }
    }
}

// ---------------- attention dots ----------------
__global__ void k_attn1(const float* __restrict__ h1, const float* __restrict__ al,
                        const float* __restrict__ ar, float* __restrict__ el,
                        float* __restrict__ er) {
    int w = (blockIdx.x * blockDim.x + threadIdx.x) >> 5;
    if (w >= NN) return;
    int lane = threadIdx.x & 31;
    const float4* hp = (const float4*)(h1 + (size_t)w * F1);
    const float4* al4 = (const float4*)al;
    const float4* ar4 = (const float4*)ar;
    float4 h0 = hp[lane], h1v = hp[lane + 32];
    float4 a0 = al4[lane], a1 = al4[lane + 32];
    float4 r0 = ar4[lane], r1 = ar4[lane + 32];
    float elA = h0.x * a0.x + h0.y * a0.y + h0.z * a0.z + h0.w * a0.w;
    float elB = h1v.x * a1.x + h1v.y * a1.y + h1v.z * a1.z + h1v.w * a1.w;
    float erA = h0.x * r0.x + h0.y * r0.y + h0.z * r0.z + h0.w * r0.w;
    float erB = h1v.x * r1.x + h1v.y * r1.y + h1v.z * r1.z + h1v.w * r1.w;
    #pragma unroll
    for (int o = 4; o; o >>= 1) {
        elA += __shfl_xor_sync(FULL, elA, o);
        elB += __shfl_xor_sync(FULL, elB, o);
        erA += __shfl_xor_sync(FULL, erA, o);
        erB += __shfl_xor_sync(FULL, erB, o);
    }
    if ((lane & 7) == 0) {
        int h = lane >> 3;
        el[w * 8 + h]     = elA;
        el[w * 8 + 4 + h] = elB;
        er[w * 8 + h]     = erA;
        er[w * 8 + 4 + h] = erB;
    }
}

__global__ void k_attn2(const float* __restrict__ h2res, const float* __restrict__ al,
                        const float* __restrict__ ar, float* __restrict__ el,
                        float* __restrict__ er) {
    int w = (blockIdx.x * blockDim.x + threadIdx.x) >> 5;
    if (w >= NN) return;
    int lane = threadIdx.x & 31;
    const float2* hp = (const float2*)(h2res + (size_t)w * 128);
    float2 h = hp[lane];
    float2 av = ((const float2*)al)[lane];
    float2 rv = ((const float2*)ar)[lane];
    float a = h.x * av.x + h.y * av.y;
    float b = h.x * rv.x + h.y * rv.y;
    #pragma unroll
    for (int o = 16; o; o >>= 1) {
        a += __shfl_xor_sync(FULL, a, o);
        b += __shfl_xor_sync(FULL, b, o);
    }
    if (lane == 0) { el[w] = a; er[w] = b; }
}

// ---------------- layer-1 aggregation: single-pass, 4-edge unrolled ----------------
__global__ __launch_bounds__(256)
void k_agg1(const int* __restrict__ us, const int* __restrict__ off,
            const float* __restrict__ h1, const float* __restrict__ el,
            const float* __restrict__ er, const float* __restrict__ feats,
            const float* __restrict__ bias, float* __restrict__ x1) {
    int w = (blockIdx.x * blockDim.x + threadIdx.x) >> 5;
    if (w >= NN) return;
    int lane = threadIdx.x & 31;
    int s0 = off[w], s1 = off[w + 1];
    int hA = lane >> 3, hB = 4 + (lane >> 3);

    float er_l = (lane < 8) ? er[w * 8 + lane] : 0.f;
    float s_l = 0.f;
    float4 acc0 = make_float4(0.f, 0.f, 0.f, 0.f);
    float4 acc1 = make_float4(0.f, 0.f, 0.f, 0.f);

    int i = s0;
    for (; i + 4 <= s1; i += 4) {
        int u0 = us[i], u1 = us[i + 1], u2 = us[i + 2], u3 = us[i + 3];
        float e0 = 0.f, e1 = 0.f, e2 = 0.f, e3 = 0.f;
        if (lane < 8) {
            e0 = el[u0 * 8 + lane];
            e1 = el[u1 * 8 + lane];
            e2 = el[u2 * 8 + lane];
            e3 = el[u3 * 8 + lane];
        }
        const float4* p0 = (const float4*)(h1 + (size_t)u0 * F1);
        const float4* p1 = (const float4*)(h1 + (size_t)u1 * F1);
        const float4* p2 = (const float4*)(h1 + (size_t)u2 * F1);
        const float4* p3 = (const float4*)(h1 + (size_t)u3 * F1);
        float4 x0 = p0[lane], y0 = p0[lane + 32];
        float4 x1v = p1[lane], y1 = p1[lane + 32];
        float4 x2 = p2[lane], y2 = p2[lane + 32];
        float4 x3 = p3[lane], y3 = p3[lane + 32];

        float t0 = e0 + er_l; t0 = t0 > 0.f ? t0 : NEG * t0;
        float t1 = e1 + er_l; t1 = t1 > 0.f ? t1 : NEG * t1;
        float t2 = e2 + er_l; t2 = t2 > 0.f ? t2 : NEG * t2;
        float t3 = e3 + er_l; t3 = t3 > 0.f ? t3 : NEG * t3;
        float w0 = __expf(t0), w1 = __expf(t1), w2 = __expf(t2), w3 = __expf(t3);
        s_l += (w0 + w1) + (w2 + w3);

        float a0A = __shfl_sync(FULL, w0, hA), a0B = __shfl_sync(FULL, w0, hB);
        float a1A = __shfl_sync(FULL, w1, hA), a1B = __shfl_sync(FULL, w1, hB);
        float a2A = __shfl_sync(FULL, w2, hA), a2B = __shfl_sync(FULL, w2, hB);
        float a3A = __shfl_sync(FULL, w3, hA), a3B = __shfl_sync(FULL, w3, hB);

        acc0.x += x0.x * a0A + x1v.x * a1A + x2.x * a2A + x3.x * a3A;
        acc0.y += x0.y * a0A + x1v.y * a1A + x2.y * a2A + x3.y * a3A;
        acc0.z += x0.z * a0A + x1v.z * a1A + x2.z * a2A + x3.z * a3A;
        acc0.w += x0.w * a0A + x1v.w * a1A + x2.w * a2A + x3.w * a3A;
        acc1.x += y0.x * a0B + y1.x * a1B + y2.x * a2B + y3.x * a3B;
        acc1.y += y0.y * a0B + y1.y * a1B + y2.y * a2B + y3.y * a3B;
        acc1.z += y0.z * a0B + y1.z * a1B + y2.z * a2B + y3.z * a3B;
        acc1.w += y0.w * a0B + y1.w * a1B + y2.w * a2B + y3.w * a3B;
    }
    for (; i < s1; i++) {
        int u = us[i];
        float e = (lane < 8) ? el[u * 8 + lane] : 0.f;
        const float4* hu = (const float4*)(h1 + (size_t)u * F1);
        float4 b0 = hu[lane], b1 = hu[lane + 32];
        float tt = e + er_l;
        tt = tt > 0.f ? tt : NEG * tt;
        float ewl = __expf(tt);
        s_l += ewl;
        float aA = __shfl_sync(FULL, ewl, hA);
        float aB = __shfl_sync(FULL, ewl, hB);
        acc0.x += b0.x * aA; acc0.y += b0.y * aA; acc0.z += b0.z * aA; acc0.w += b0.w * aA;
        acc1.x += b1.x * aB; acc1.y += b1.y * aB; acc1.z += b1.z * aB; acc1.w += b1.w * aB;
    }

    float is_l = (lane < 8) ? 1.f / s_l : 0.f;
    float isA = __shfl_sync(FULL, is_l, hA);
    float isB = __shfl_sync(FULL, is_l, hB);

    const float4* fp = (const float4*)(feats + (size_t)w * FIN);
    const float4* bp = (const float4*)bias;
    float4 f0 = fp[lane], f1 = fp[lane + 32];
    float4 bA = bp[lane], bB = bp[lane + 32];
    float4 o0, o1;
    o0.x = acc0.x * isA + f0.x + bA.x;  o0.y = acc0.y * isA + f0.y + bA.y;
    o0.z = acc0.z * isA + f0.z + bA.z;  o0.w = acc0.w * isA + f0.w + bA.w;
    o1.x = acc1.x * isB + f1.x + bB.x;  o1.y = acc1.y * isB + f1.y + bB.y;
    o1.z = acc1.z * isB + f1.z + bB.z;  o1.w = acc1.w * isB + f1.w + bB.w;
    o0.x = o0.x > 0.f ? o0.x : expm1f(o0.x);
    o0.y = o0.y > 0.f ? o0.y : expm1f(o0.y);
    o0.z = o0.z > 0.f ? o0.z : expm1f(o0.z);
    o0.w = o0.w > 0.f ? o0.w : expm1f(o0.w);
    o1.x = o1.x > 0.f ? o1.x : expm1f(o1.x);
    o1.y = o1.y > 0.f ? o1.y : expm1f(o1.y);
    o1.z = o1.z > 0.f ? o1.z : expm1f(o1.z);
    o1.w = o1.w > 0.f ? o1.w : expm1f(o1.w);
    float4* xp = (float4*)(x1 + (size_t)w * F1);
    xp[lane] = o0;
    xp[lane + 32] = o1;
}

// ---------------- concat [W2 | res_W2] ----------------
__global__ void k_concat(const float* __restrict__ W2, const float* __restrict__ rw,
                         float* __restrict__ Bcat) {
    int i = blockIdx.x * blockDim.x + threadIdx.x;
    if (i < FIN * 128) {
        int k = i >> 7, c = i & 127;
        Bcat[i] = (c < 64) ? W2[k * 64 + c] : rw[k * 64 + (c - 64)];
    }
}

// ---------------- layer-2 aggregation: single-pass, 4-edge unrolled ----------------
__global__ __launch_bounds__(256)
void k_agg2(const int* __restrict__ us, const int* __restrict__ off,
            const float* __restrict__ h2res, const float* __restrict__ el,
            const float* __restrict__ er, const float* __restrict__ bias,
            float* __restrict__ out) {
    int w = (blockIdx.x * blockDim.x + threadIdx.x) >> 5;
    if (w >= NN) return;
    int lane = threadIdx.x & 31;
    int s0 = off[w], s1 = off[w + 1];
    float erv = er[w];
    float s = 0.f;
    float2 acc = make_float2(0.f, 0.f);

    int i = s0;
    for (; i + 4 <= s1; i += 4) {
        int u0 = us[i], u1 = us[i + 1], u2 = us[i + 2], u3 = us[i + 3];
        float e0 = el[u0], e1 = el[u1], e2 = el[u2], e3 = el[u3];
        float2 b0 = *(const float2*)&h2res[(size_t)u0 * 128 + 2 * lane];
        float2 b1 = *(const float2*)&h2res[(size_t)u1 * 128 + 2 * lane];
        float2 b2 = *(const float2*)&h2res[(size_t)u2 * 128 + 2 * lane];
        float2 b3 = *(const float2*)&h2res[(size_t)u3 * 128 + 2 * lane];
        float t0 = e0 + erv; t0 = t0 > 0.f ? t0 : NEG * t0;
        float t1 = e1 + erv; t1 = t1 > 0.f ? t1 : NEG * t1;
        float t2 = e2 + erv; t2 = t2 > 0.f ? t2 : NEG * t2;
        float t3 = e3 + erv; t3 = t3 > 0.f ? t3 : NEG * t3;
        float w0 = __expf(t0), w1 = __expf(t1), w2 = __expf(t2), w3 = __expf(t3);
        s += (w0 + w1) + (w2 + w3);
        acc.x += b0.x * w0 + b1.x * w1 + b2.x * w2 + b3.x * w3;
        acc.y += b0.y * w0 + b1.y * w1 + b2.y * w2 + b3.y * w3;
    }
    for (; i < s1; i++) {
        int u = us[i];
        float tt = el[u] + erv;
        tt = tt > 0.f ? tt : NEG * tt;
        float e = __expf(tt);
        s += e;
        float2 b = *(const float2*)&h2res[(size_t)u * 128 + 2 * lane];
        acc.x += b.x * e;
        acc.y += b.y * e;
    }
    float is = 1.f / s;
    float2 rv = *(const float2*)&h2res[(size_t)w * 128 + 64 + 2 * lane];
    float2 bv = *(const float2*)&bias[2 * lane];
    float2 o;
    o.x = acc.x * is + rv.x + bv.x;
    o.y = acc.y * is + rv.y + bv.y;
    *(float2*)&out[(size_t)w * 64 + 2 * lane] = o;
}

// ---------------- launch (R5-identical structure) ----------------
extern "C" void kernel_launch(void* const* d_in, const int* in_sizes, int n_in,
                              void* d_out, int out_size) {
    const float* feats = (const float*)d_in[0];
    const int*   src   = (const int*)d_in[1];
    const int*   dst   = (const int*)d_in[2];
    const float* W1    = (const float*)d_in[3];
    const float* al1   = (const float*)d_in[4];
    const float* ar1   = (const float*)d_in[5];
    const float* b1    = (const float*)d_in[6];
    const float* W2    = (const float*)d_in[7];
    const float* al2   = (const float*)d_in[8];
    const float* ar2   = (const float*)d_in[9];
    const float* b2    = (const float*)d_in[10];
    const float* rw2   = (const float*)d_in[11];
    float* out = (float*)d_out;
    int E = in_sizes[1];

    float *h1, *el1, *er1, *x1, *h2res, *el2, *er2, *Bcat;
    int *deg, *off, *us;
    cudaGetSymbolAddress((void**)&h1, g_h1);
    cudaGetSymbolAddress((void**)&el1, g_el1);
    cudaGetSymbolAddress((void**)&er1, g_er1);
    cudaGetSymbolAddress((void**)&x1, g_x1);
    cudaGetSymbolAddress((void**)&h2res, g_h2res);
    cudaGetSymbolAddress((void**)&el2, g_el2);
    cudaGetSymbolAddress((void**)&er2, g_er2);
    cudaGetSymbolAddress((void**)&Bcat, g_Bcat);
    cudaGetSymbolAddress((void**)&deg, g_deg);
    cudaGetSymbolAddress((void**)&off, g_off);
    cudaGetSymbolAddress((void**)&us, g_us);

    static cudaStream_t side = nullptr;
    static cudaEvent_t evFork = nullptr, evJoin = nullptr;
    if (!side) {
        cudaStreamCreateWithFlags(&side, cudaStreamNonBlocking);
        cudaEventCreateWithFlags(&evFork, cudaEventDisableTiming);
        cudaEventCreateWithFlags(&evJoin, cudaEventDisableTiming);
    }

    int eb = (E + 255) / 256;
    int wb = (NN * 32 + 255) / 256;

    // fork: CSR build + weight concat on side stream
    cudaEventRecord(evFork, 0);
    cudaStreamWaitEvent(side, evFork, 0);
    cudaMemsetAsync(deg, 0, NN * sizeof(int), side);
    k_hist<<<eb, 256, 0, side>>>(dst, E, deg);
    k_scan<<<1, 1024, 0, side>>>(deg, off, NN);
    cudaMemsetAsync(deg, 0, NN * sizeof(int), side);
    k_scatter<<<eb, 256, 0, side>>>(src, dst, E, off, deg, us);
    k_concat<<<(FIN * 128 + 255) / 256, 256, 0, side>>>(W2, rw2, Bcat);
    cudaEventRecord(evJoin, side);

    // main stream: layer-1 dense part
    k_mma_gemm<<<dim3((NN + 127) / 128, F1 / 64), 256>>>(feats, W1, h1, NN, F1, FIN);
    k_attn1<<<wb, 256>>>(h1, al1, ar1, el1, er1);

    cudaStreamWaitEvent(0, evJoin, 0);
    k_agg1<<<wb, 256>>>(us, off, h1, el1, er1, feats, b1, x1);

    // layer 2
    k_mma_gemm<<<dim3((NN + 127) / 128, 128 / 64), 256>>>(x1, Bcat, h2res, NN, 128, FIN);
    k_attn2<<<wb, 256>>>(h2res, al2, ar2, el2, er2);
    k_agg2<<<wb, 256>>>(us, off, h2res, el2, er2, b2, out);
}

// round 13
// speedup vs baseline: 1.4636x; 1.4636x over previous
#include <cuda_runtime.h>
#include <math.h>

#define NN   50000
#define FIN  256
#define H1N  8
#define F1   256
#define NEG  0.2f
#define EMAX 900000
#define FULL 0xffffffffu
#define NB_SCAN ((NN + 1023) / 1024)

// ---------------- scratch ----------------
__device__ __align__(256) float g_h1[NN * F1];
__device__ __align__(256) float g_el1[NN * H1N];
__device__ __align__(256) float g_er1[NN * H1N];
__device__ __align__(256) float g_x1[NN * F1];
__device__ __align__(256) float g_h2res[NN * 128];   // [h2 (64) | residual (64)]
__device__ __align__(256) float g_el2[NN];
__device__ __align__(256) float g_er2[NN];
__device__ __align__(256) float g_Bcat[FIN * 128];
__device__ int g_deg[NN];
__device__ int g_off[NN + 1];
__device__ int g_bsum[64];
__device__ int g_us[EMAX];

// ---------------- CSR build ----------------
__global__ void k_hist(const int* __restrict__ dst, int E, int* __restrict__ deg) {
    int i = blockIdx.x * blockDim.x + threadIdx.x;
    if (i < E) atomicAdd(&deg[dst[i]], 1);
}

// multi-block scan: per-block exclusive scan + block totals
__global__ void k_scan_blk(const int* __restrict__ deg, int* __restrict__ off,
                           int* __restrict__ bsum, int n) {
    __shared__ int wsum[32];
    int tid = threadIdx.x, lane = tid & 31, wid = tid >> 5;
    int i = blockIdx.x * 1024 + tid;
    int v = (i < n) ? deg[i] : 0;
    int x = v;
    #pragma unroll
    for (int o = 1; o < 32; o <<= 1) {
        int y = __shfl_up_sync(FULL, x, o);
        if (lane >= o) x += y;
    }
    if (lane == 31) wsum[wid] = x;
    __syncthreads();
    if (wid == 0) {
        int w = wsum[lane];
        #pragma unroll
        for (int o = 1; o < 32; o <<= 1) {
            int y = __shfl_up_sync(FULL, w, o);
            if (lane >= o) w += y;
        }
        wsum[lane] = w;
    }
    __syncthreads();
    int incl = x + (wid ? wsum[wid - 1] : 0);
    if (i < n) off[i] = incl - v;
    if (tid == 1023) bsum[blockIdx.x] = incl;
}

__global__ void k_scan_top(int* __restrict__ bsum, int nb) {
    if (threadIdx.x == 0) {
        int run = 0;
        for (int b = 0; b < nb; b++) {
            int t = bsum[b];
            bsum[b] = run;
            run += t;
        }
    }
}

__global__ void k_scan_add(int* __restrict__ off, const int* __restrict__ bsum,
                           int n, int E) {
    int i = blockIdx.x * 1024 + threadIdx.x;
    if (i < n) off[i] += bsum[blockIdx.x];
    if (i == 0) off[n] = E;
}

__global__ void k_scatter(const int* __restrict__ src, const int* __restrict__ dst,
                          int E, const int* __restrict__ off, int* __restrict__ cur,
                          int* __restrict__ us) {
    int i = blockIdx.x * blockDim.x + threadIdx.x;
    if (i < E) {
        int d = dst[i];
        int p = off[d] + atomicAdd(&cur[d], 1);
        us[p] = src[i];
    }
}

// ---------------- TF32 tensor-core GEMM (R5-identical) ----------------
__device__ __forceinline__ unsigned f2tf(float x) {
    unsigned u;
    asm("cvt.rna.tf32.f32 %0, %1;" : "=r"(u) : "f"(x));
    return u;
}

__device__ __forceinline__ void mma_tf32(float* d, const unsigned* a, const unsigned* b) {
    asm volatile(
        "mma.sync.aligned.m16n8k8.row.col.f32.tf32.tf32.f32 "
        "{%0,%1,%2,%3}, {%4,%5,%6,%7}, {%8,%9}, {%0,%1,%2,%3};\n"
        : "+f"(d[0]), "+f"(d[1]), "+f"(d[2]), "+f"(d[3])
        : "r"(a[0]), "r"(a[1]), "r"(a[2]), "r"(a[3]), "r"(b[0]), "r"(b[1]));
}

__global__ __launch_bounds__(256)
void k_mma_gemm(const float* __restrict__ A, const float* __restrict__ B,
                float* __restrict__ C, int M, int N, int K) {
    __shared__ unsigned As[128][36];
    __shared__ unsigned Bs[32][72];
    int t = threadIdx.x;
    int lane = t & 31;
    int warp = t >> 5;
    int g = lane >> 2, q = lane & 3;
    int warpM = warp & 3, warpN = warp >> 2;
    int bm = blockIdx.x * 128, bn = blockIdx.y * 64;

    float4 avs[4], bvs[2];
    float acc[2][4][4] = {};

    auto loadA = [&](int kt) {
        #pragma unroll
        for (int i = 0; i < 4; i++) {
            int idx = t + i * 256;
            int r = idx >> 3, c4 = (idx & 7) * 4;
            float4 v = make_float4(0.f, 0.f, 0.f, 0.f);
            if (bm + r < M)
                v = *(const float4*)&A[(size_t)(bm + r) * K + kt + c4];
            avs[i] = v;
        }
    };
    auto loadB = [&](int kt) {
        #pragma unroll
        for (int i = 0; i < 2; i++) {
            int idx = t + i * 256;
            int r = idx >> 4, c4 = (idx & 15) * 4;
            bvs[i] = *(const float4*)&B[(size_t)(kt + r) * N + bn + c4];
        }
    };
    auto stage = [&]() {
        #pragma unroll
        for (int i = 0; i < 4; i++) {
            int idx = t + i * 256;
            int r = idx >> 3, c4 = (idx & 7) * 4;
            As[r][c4 + 0] = f2tf(avs[i].x);
            As[r][c4 + 1] = f2tf(avs[i].y);
            As[r][c4 + 2] = f2tf(avs[i].z);
            As[r][c4 + 3] = f2tf(avs[i].w);
        }
        #pragma unroll
        for (int i = 0; i < 2; i++) {
            int idx = t + i * 256;
            int r = idx >> 4, c4 = (idx & 15) * 4;
            Bs[r][c4 + 0] = f2tf(bvs[i].x);
            Bs[r][c4 + 1] = f2tf(bvs[i].y);
            Bs[r][c4 + 2] = f2tf(bvs[i].z);
            Bs[r][c4 + 3] = f2tf(bvs[i].w);
        }
    };

    loadA(0); loadB(0);
    stage();
    __syncthreads();

    for (int kt = 0; kt < K; kt += 32) {
        bool nxt = (kt + 32) < K;
        if (nxt) { loadA(kt + 32); loadB(kt + 32); }

        #pragma unroll
        for (int ks = 0; ks < 4; ks++) {
            int k0 = ks * 8;
            unsigned af[2][4], bf[4][2];
            #pragma unroll
            for (int mt = 0; mt < 2; mt++) {
                int rb = warpM * 32 + mt * 16;
                af[mt][0] = As[rb + g][k0 + q];
                af[mt][1] = As[rb + g + 8][k0 + q];
                af[mt][2] = As[rb + g][k0 + q + 4];
                af[mt][3] = As[rb + g + 8][k0 + q + 4];
            }
            #pragma unroll
            for (int nt = 0; nt < 4; nt++) {
                int cb = warpN * 32 + nt * 8;
                bf[nt][0] = Bs[k0 + q][cb + g];
                bf[nt][1] = Bs[k0 + q + 4][cb + g];
            }
            #pragma unroll
            for (int mt = 0; mt < 2; mt++)
                #pragma unroll
                for (int nt = 0; nt < 4; nt++)
                    mma_tf32(acc[mt][nt], af[mt], bf[nt]);
        }
        if (nxt) {
            __syncthreads();
            stage();
            __syncthreads();
        }
    }

    #pragma unroll
    for (int mt = 0; mt < 2; mt++) {
        int r0 = bm + warpM * 32 + mt * 16 + g;
        #pragma unroll
        for (int nt = 0; nt < 4; nt++) {
            int c = bn + warpN * 32 + nt * 8 + q * 2;
            if (r0 < M)
                *(float2*)&C[(size_t)r0 * N + c] = make_float2(acc[mt][nt][0], acc[mt][nt][1]);
            if (r0 + 8 < M)
                *(float2*)&C[(size_t)(r0 + 8) * N + c] = make_float2(acc[mt][nt][2], acc[mt][nt][3]);
        }
    }
}

// ---------------- attention dots (R5-identical) ----------------
__global__ void k_attn1(const float* __restrict__ h1, const float* __restrict__ al,
                        const float* __restrict__ ar, float* __restrict__ el,
                        float* __restrict__ er) {
    int w = (blockIdx.x * blockDim.x + threadIdx.x) >> 5;
    if (w >= NN) return;
    int lane = threadIdx.x & 31;
    const float4* hp = (const float4*)(h1 + (size_t)w * F1);
    const float4* al4 = (const float4*)al;
    const float4* ar4 = (const float4*)ar;
    float4 h0 = hp[lane], h1v = hp[lane + 32];
    float4 a0 = al4[lane], a1 = al4[lane + 32];
    float4 r0 = ar4[lane], r1 = ar4[lane + 32];
    float elA = h0.x * a0.x + h0.y * a0.y + h0.z * a0.z + h0.w * a0.w;
    float elB = h1v.x * a1.x + h1v.y * a1.y + h1v.z * a1.z + h1v.w * a1.w;
    float erA = h0.x * r0.x + h0.y * r0.y + h0.z * r0.z + h0.w * r0.w;
    float erB = h1v.x * r1.x + h1v.y * r1.y + h1v.z * r1.z + h1v.w * r1.w;
    #pragma unroll
    for (int o = 4; o; o >>= 1) {
        elA += __shfl_xor_sync(FULL, elA, o);
        elB += __shfl_xor_sync(FULL, elB, o);
        erA += __shfl_xor_sync(FULL, erA, o);
        erB += __shfl_xor_sync(FULL, erB, o);
    }
    if ((lane & 7) == 0) {
        int h = lane >> 3;
        el[w * 8 + h]     = elA;
        el[w * 8 + 4 + h] = elB;
        er[w * 8 + h]     = erA;
        er[w * 8 + 4 + h] = erB;
    }
}

__global__ void k_attn2(const float* __restrict__ h2res, const float* __restrict__ al,
                        const float* __restrict__ ar, float* __restrict__ el,
                        float* __restrict__ er) {
    int w = (blockIdx.x * blockDim.x + threadIdx.x) >> 5;
    if (w >= NN) return;
    int lane = threadIdx.x & 31;
    const float2* hp = (const float2*)(h2res + (size_t)w * 128);
    float2 h = hp[lane];
    float2 av = ((const float2*)al)[lane];
    float2 rv = ((const float2*)ar)[lane];
    float a = h.x * av.x + h.y * av.y;
    float b = h.x * rv.x + h.y * rv.y;
    #pragma unroll
    for (int o = 16; o; o >>= 1) {
        a += __shfl_xor_sync(FULL, a, o);
        b += __shfl_xor_sync(FULL, b, o);
    }
    if (lane == 0) { el[w] = a; er[w] = b; }
}

// ---------------- layer-1 aggregation: no-shuffle, lane-owns-head, fp32 ----------
// lane covers features f = lane*8 .. lane*8+7, all in head h = lane>>2.
__global__ __launch_bounds__(256)
void k_agg1(const int* __restrict__ us, const int* __restrict__ off,
            const float* __restrict__ h1, const float* __restrict__ el,
            const float* __restrict__ er, const float* __restrict__ feats,
            const float* __restrict__ bias, float* __restrict__ x1) {
    int w = (blockIdx.x * blockDim.x + threadIdx.x) >> 5;
    if (w >= NN) return;
    int lane = threadIdx.x & 31;
    int h = lane >> 2;
    int s0 = off[w], s1 = off[w + 1];
    float er_l = er[w * 8 + h];
    float s_l = 0.f;
    float acc[8] = {};

    int i = s0;
    for (; i + 4 <= s1; i += 4) {
        int u0 = us[i], u1 = us[i + 1], u2 = us[i + 2], u3 = us[i + 3];
        float e0 = el[u0 * 8 + h];
        float e1 = el[u1 * 8 + h];
        float e2 = el[u2 * 8 + h];
        float e3 = el[u3 * 8 + h];
        const float4* p0 = (const float4*)(h1 + (size_t)u0 * F1 + lane * 8);
        const float4* p1 = (const float4*)(h1 + (size_t)u1 * F1 + lane * 8);
        const float4* p2 = (const float4*)(h1 + (size_t)u2 * F1 + lane * 8);
        const float4* p3 = (const float4*)(h1 + (size_t)u3 * F1 + lane * 8);
        float4 a0 = p0[0], b0 = p0[1];
        float4 a1 = p1[0], b1 = p1[1];
        float4 a2 = p2[0], b2 = p2[1];
        float4 a3 = p3[0], b3 = p3[1];

        float t0 = e0 + er_l; t0 = t0 > 0.f ? t0 : NEG * t0;
        float t1 = e1 + er_l; t1 = t1 > 0.f ? t1 : NEG * t1;
        float t2 = e2 + er_l; t2 = t2 > 0.f ? t2 : NEG * t2;
        float t3 = e3 + er_l; t3 = t3 > 0.f ? t3 : NEG * t3;
        float w0 = __expf(t0), w1 = __expf(t1), w2 = __expf(t2), w3 = __expf(t3);
        s_l += (w0 + w1) + (w2 + w3);

        acc[0] += a0.x * w0 + a1.x * w1 + a2.x * w2 + a3.x * w3;
        acc[1] += a0.y * w0 + a1.y * w1 + a2.y * w2 + a3.y * w3;
        acc[2] += a0.z * w0 + a1.z * w1 + a2.z * w2 + a3.z * w3;
        acc[3] += a0.w * w0 + a1.w * w1 + a2.w * w2 + a3.w * w3;
        acc[4] += b0.x * w0 + b1.x * w1 + b2.x * w2 + b3.x * w3;
        acc[5] += b0.y * w0 + b1.y * w1 + b2.y * w2 + b3.y * w3;
        acc[6] += b0.z * w0 + b1.z * w1 + b2.z * w2 + b3.z * w3;
        acc[7] += b0.w * w0 + b1.w * w1 + b2.w * w2 + b3.w * w3;
    }
    for (; i < s1; i++) {
        int u = us[i];
        float e = el[u * 8 + h];
        const float4* p = (const float4*)(h1 + (size_t)u * F1 + lane * 8);
        float4 a = p[0], b = p[1];
        float tt = e + er_l;
        tt = tt > 0.f ? tt : NEG * tt;
        float ww = __expf(tt);
        s_l += ww;
        acc[0] += a.x * ww; acc[1] += a.y * ww; acc[2] += a.z * ww; acc[3] += a.w * ww;
        acc[4] += b.x * ww; acc[5] += b.y * ww; acc[6] += b.z * ww; acc[7] += b.w * ww;
    }

    float is = 1.f / s_l;
    int f = lane * 8;
    float4 f0 = *(const float4*)&feats[(size_t)w * FIN + f];
    float4 f1 = *(const float4*)&feats[(size_t)w * FIN + f + 4];
    float4 bA = *(const float4*)&bias[f];
    float4 bB = *(const float4*)&bias[f + 4];
    float o[8];
    o[0] = acc[0] * is + f0.x + bA.x;
    o[1] = acc[1] * is + f0.y + bA.y;
    o[2] = acc[2] * is + f0.z + bA.z;
    o[3] = acc[3] * is + f0.w + bA.w;
    o[4] = acc[4] * is + f1.x + bB.x;
    o[5] = acc[5] * is + f1.y + bB.y;
    o[6] = acc[6] * is + f1.z + bB.z;
    o[7] = acc[7] * is + f1.w + bB.w;
    #pragma unroll
    for (int j = 0; j < 8; j++)
        o[j] = o[j] > 0.f ? o[j] : expm1f(o[j]);
    *(float4*)&x1[(size_t)w * F1 + f]     = make_float4(o[0], o[1], o[2], o[3]);
    *(float4*)&x1[(size_t)w * F1 + f + 4] = make_float4(o[4], o[5], o[6], o[7]);
}

// ---------------- concat [W2 | res_W2] ----------------
__global__ void k_concat(const float* __restrict__ W2, const float* __restrict__ rw,
                         float* __restrict__ Bcat) {
    int i = blockIdx.x * blockDim.x + threadIdx.x;
    if (i < FIN * 128) {
        int k = i >> 7, c = i & 127;
        Bcat[i] = (c < 64) ? W2[k * 64 + c] : rw[k * 64 + (c - 64)];
    }
}

// ---------------- layer-2 aggregation (R5-identical) ----------------
__global__ __launch_bounds__(256)
void k_agg2(const int* __restrict__ us, const int* __restrict__ off,
            const float* __restrict__ h2res, const float* __restrict__ el,
            const float* __restrict__ er, const float* __restrict__ bias,
            float* __restrict__ out) {
    int w = (blockIdx.x * blockDim.x + threadIdx.x) >> 5;
    if (w >= NN) return;
    int lane = threadIdx.x & 31;
    int s0 = off[w], s1 = off[w + 1];
    float erv = er[w];
    float s = 0.f;
    float2 acc = make_float2(0.f, 0.f);

    int i = s0;
    for (; i + 4 <= s1; i += 4) {
        int u0 = us[i], u1 = us[i + 1], u2 = us[i + 2], u3 = us[i + 3];
        float e0 = el[u0], e1 = el[u1], e2 = el[u2], e3 = el[u3];
        float2 b0 = *(const float2*)&h2res[(size_t)u0 * 128 + 2 * lane];
        float2 b1 = *(const float2*)&h2res[(size_t)u1 * 128 + 2 * lane];
        float2 b2 = *(const float2*)&h2res[(size_t)u2 * 128 + 2 * lane];
        float2 b3 = *(const float2*)&h2res[(size_t)u3 * 128 + 2 * lane];
        float t0 = e0 + erv; t0 = t0 > 0.f ? t0 : NEG * t0;
        float t1 = e1 + erv; t1 = t1 > 0.f ? t1 : NEG * t1;
        float t2 = e2 + erv; t2 = t2 > 0.f ? t2 : NEG * t2;
        float t3 = e3 + erv; t3 = t3 > 0.f ? t3 : NEG * t3;
        float w0 = __expf(t0), w1 = __expf(t1), w2 = __expf(t2), w3 = __expf(t3);
        s += (w0 + w1) + (w2 + w3);
        acc.x += b0.x * w0 + b1.x * w1 + b2.x * w2 + b3.x * w3;
        acc.y += b0.y * w0 + b1.y * w1 + b2.y * w2 + b3.y * w3;
    }
    for (; i < s1; i++) {
        int u = us[i];
        float tt = el[u] + erv;
        tt = tt > 0.f ? tt : NEG * tt;
        float e = __expf(tt);
        s += e;
        float2 b = *(const float2*)&h2res[(size_t)u * 128 + 2 * lane];
        acc.x += b.x * e;
        acc.y += b.y * e;
    }
    float is = 1.f / s;
    float2 rv = *(const float2*)&h2res[(size_t)w * 128 + 64 + 2 * lane];
    float2 bv = *(const float2*)&bias[2 * lane];
    float2 o;
    o.x = acc.x * is + rv.x + bv.x;
    o.y = acc.y * is + rv.y + bv.y;
    *(float2*)&out[(size_t)w * 64 + 2 * lane] = o;
}

// ---------------- launch (R5 structure; scan split into 3 kernels) ----------------
extern "C" void kernel_launch(void* const* d_in, const int* in_sizes, int n_in,
                              void* d_out, int out_size) {
    const float* feats = (const float*)d_in[0];
    const int*   src   = (const int*)d_in[1];
    const int*   dst   = (const int*)d_in[2];
    const float* W1    = (const float*)d_in[3];
    const float* al1   = (const float*)d_in[4];
    const float* ar1   = (const float*)d_in[5];
    const float* b1    = (const float*)d_in[6];
    const float* W2    = (const float*)d_in[7];
    const float* al2   = (const float*)d_in[8];
    const float* ar2   = (const float*)d_in[9];
    const float* b2    = (const float*)d_in[10];
    const float* rw2   = (const float*)d_in[11];
    float* out = (float*)d_out;
    int E = in_sizes[1];

    float *h1, *el1, *er1, *x1, *h2res, *el2, *er2, *Bcat;
    int *deg, *off, *us, *bsum;
    cudaGetSymbolAddress((void**)&h1, g_h1);
    cudaGetSymbolAddress((void**)&el1, g_el1);
    cudaGetSymbolAddress((void**)&er1, g_er1);
    cudaGetSymbolAddress((void**)&x1, g_x1);
    cudaGetSymbolAddress((void**)&h2res, g_h2res);
    cudaGetSymbolAddress((void**)&el2, g_el2);
    cudaGetSymbolAddress((void**)&er2, g_er2);
    cudaGetSymbolAddress((void**)&Bcat, g_Bcat);
    cudaGetSymbolAddress((void**)&deg, g_deg);
    cudaGetSymbolAddress((void**)&off, g_off);
    cudaGetSymbolAddress((void**)&bsum, g_bsum);
    cudaGetSymbolAddress((void**)&us, g_us);

    static cudaStream_t side = nullptr;
    static cudaEvent_t evFork = nullptr, evJoin = nullptr;
    if (!side) {
        cudaStreamCreateWithFlags(&side, cudaStreamNonBlocking);
        cudaEventCreateWithFlags(&evFork, cudaEventDisableTiming);
        cudaEventCreateWithFlags(&evJoin, cudaEventDisableTiming);
    }

    int eb = (E + 255) / 256;
    int wb = (NN * 32 + 255) / 256;

    // fork: CSR build + weight concat on side stream
    cudaEventRecord(evFork, 0);
    cudaStreamWaitEvent(side, evFork, 0);
    cudaMemsetAsync(deg, 0, NN * sizeof(int), side);
    k_hist<<<eb, 256, 0, side>>>(dst, E, deg);
    k_scan_blk<<<NB_SCAN, 1024, 0, side>>>(deg, off, bsum, NN);
    k_scan_top<<<1, 32, 0, side>>>(bsum, NB_SCAN);
    k_scan_add<<<NB_SCAN, 1024, 0, side>>>(off, bsum, NN, E);
    cudaMemsetAsync(deg, 0, NN * sizeof(int), side);
    k_scatter<<<eb, 256, 0, side>>>(src, dst, E, off, deg, us);
    k_concat<<<(FIN * 128 + 255) / 256, 256, 0, side>>>(W2, rw2, Bcat);
    cudaEventRecord(evJoin, side);

    // main stream: layer-1 dense part
    k_mma_gemm<<<dim3((NN + 127) / 128, F1 / 64), 256>>>(feats, W1, h1, NN, F1, FIN);
    k_attn1<<<wb, 256>>>(h1, al1, ar1, el1, er1);

    cudaStreamWaitEvent(0, evJoin, 0);
    k_agg1<<<wb, 256>>>(us, off, h1, el1, er1, feats, b1, x1);

    // layer 2
    k_mma_gemm<<<dim3((NN + 127) / 128, 128 / 64), 256>>>(x1, Bcat, h2res, NN, 128, FIN);
    k_attn2<<<wb, 256>>>(h2res, al2, ar2, el2, er2);
    k_agg2<<<wb, 256>>>(us, off, h2res, el2, er2, b2, out);
}